// round 13
// baseline (speedup 1.0000x reference)
#include <cuda_runtime.h>
#include <cuda_fp16.h>
#include <stdint.h>

// Problem constants
#define BATCH 4
#define SEQ   2048
#define HID   1024
#define NFREQ 513           // H/2 + 1
#define KD    1024          // 513 cos + 511 sin (sin0 == sin512 == 0 exactly)
#define ROWS  (BATCH * SEQ) // 8192

// Scratch (static __device__ — no allocations allowed)
__device__ __align__(256) __half g_qf[(size_t)ROWS * KD];         // Q phase features
__device__ __align__(256) __half g_kf[(size_t)ROWS * KD];         // K phase features
__device__ __align__(256) __half g_wh[(size_t)ROWS * SEQ];        // fp16 exp(scores)
__device__ __align__(256) __half g_vt[(size_t)BATCH * HID * SEQ]; // V^T [b][h][j] fp16
__device__ float  g_rsum[ROWS];                                   // 1/rowsum per row
__device__ float2 g_tw[768];                                      // W_1024^t, t=0..767

// ===========================================================================
// PTX helpers
// ===========================================================================
__device__ __forceinline__ uint32_t smem_u32(const void* p) {
    uint32_t a;
    asm("{ .reg .u64 t; cvta.to.shared.u64 t, %1; cvt.u32.u64 %0, t; }"
        : "=r"(a) : "l"(p));
    return a;
}
__device__ __forceinline__ uint32_t elect_one() {
    uint32_t p;
    asm volatile(
        "{\n\t.reg .pred p;\n\telect.sync _|p, 0xFFFFFFFF;\n\t"
        "selp.b32 %0, 1, 0, p;\n\t}" : "=r"(p));
    return p;
}
__device__ __forceinline__ void cp16(uint32_t dst, const void* src) {
    asm volatile("cp.async.cg.shared.global [%0], [%1], 16;" :: "r"(dst), "l"(src));
}

#define MBARRIER_INIT(addr, cnt) \
    asm volatile("mbarrier.init.shared.b64 [%0], %1;" :: "r"((uint32_t)(addr)), "r"((uint32_t)(cnt)) : "memory")
#define MBARRIER_ARRIVE(addr) \
    asm volatile("mbarrier.arrive.shared.b64 _, [%0];" :: "r"((uint32_t)(addr)) : "memory")
#define CPASYNC_MBAR_ARRIVE_NOINC(addr) \
    asm volatile("cp.async.mbarrier.arrive.noinc.shared.b64 [%0];" :: "r"((uint32_t)(addr)) : "memory")

#define MBARRIER_WAIT_PARITY(mbar_smem_addr, phase_parity) do { \
    uint32_t _mbar = (uint32_t)(mbar_smem_addr); \
    uint32_t _parity = (uint32_t)(phase_parity); \
    uint32_t _done; \
    asm volatile( \
        "{\n\t.reg .pred p;\n\t" \
        "mbarrier.try_wait.parity.acquire.cta.shared::cta.b64 p, [%1], %2;\n\t" \
        "selp.b32 %0, 1, 0, p;\n\t}" \
        : "=r"(_done) : "r"(_mbar), "r"(_parity) : "memory"); \
    if (!_done) { \
        asm volatile( \
            "{\n\t.reg .pred P1;\n\t" \
            "WAIT_LOOP_%=:\n\t" \
            "mbarrier.try_wait.parity.acquire.cta.shared::cta.b64 P1, [%0], %1, 0x989680;\n\t" \
            "@P1 bra.uni WAIT_DONE_%=;\n\t" \
            "bra.uni WAIT_LOOP_%=;\n\t" \
            "WAIT_DONE_%=:\n\t}" \
            :: "r"(_mbar), "r"(_parity) : "memory"); \
    } \
} while (0)

#define LDSM4(r, a)                                                          \
    asm volatile("ldmatrix.sync.aligned.m8n8.x4.shared.b16 {%0,%1,%2,%3}, [%4];" \
                 : "=r"((r)[0]), "=r"((r)[1]), "=r"((r)[2]), "=r"((r)[3])    \
                 : "r"(a))

// fp32-accumulate MMA
#define MMA16816(d, a0, a1, a2, a3, b0, b1)                                  \
    asm volatile(                                                            \
        "mma.sync.aligned.m16n8k16.row.col.f32.f16.f16.f32 "                 \
        "{%0,%1,%2,%3}, {%4,%5,%6,%7}, {%8,%9}, {%0,%1,%2,%3};"              \
        : "+f"((d)[0]), "+f"((d)[1]), "+f"((d)[2]), "+f"((d)[3])             \
        : "r"(a0), "r"(a1), "r"(a2), "r"(a3), "r"(b0), "r"(b1))

// fp16-accumulate MMA (full-rate path hypothesis)
#define MMA16816H(d, a0, a1, a2, a3, b0, b1)                                 \
    asm volatile(                                                            \
        "mma.sync.aligned.m16n8k16.row.col.f16.f16.f16.f16 "                 \
        "{%0,%1}, {%2,%3,%4,%5}, {%6,%7}, {%0,%1};"                          \
        : "+r"((d)[0]), "+r"((d)[1])                                         \
        : "r"(a0), "r"(a1), "r"(a2), "r"(a3), "r"(b0), "r"(b1))

// 128B-row XOR swizzle: rows 0..127, bits[6:4] ^= row&7
#define SWZ(o) ((o) ^ ((((o) >> 7) & 7) << 4))

// ===========================================================================
// Kernel 0: one-time twiddle table W_1024^t = exp(-2*pi*i*t/1024), t<768
// ===========================================================================
__global__ void twiddle_init_kernel()
{
    const int t = blockIdx.x * 256 + threadIdx.x;
    if (t < 768) {
        float s, c;
        sincosf(-6.283185307179586f * (float)t * (1.0f / 1024.0f), &s, &c);
        g_tw[t] = make_float2(c, s);
    }
}

// ===========================================================================
// Kernel 1: two real rows per block packed into ONE complex FFT-1024
// (radix-4 DIF, 5 stages), untangle at readout.
// Feature layout: dst[k] = cos_k (k=0..512), dst[512+k] = sin_k (k=1..511).
// sin_0 = sin_512 = 0 exactly -> dropped; KD = 1024 exactly.
// ===========================================================================
#define FPAD(i) ((i) + ((i) >> 4))

__global__ void fft_phase_kernel(const float* __restrict__ Q,
                                 const float* __restrict__ K)
{
    __shared__ float2 sd[1024 + 64];
    __shared__ float2 stw[768];

    const int t = threadIdx.x;                 // 256 threads
    const bool isK = blockIdx.x >= (ROWS / 2);
    const int pr = blockIdx.x & (ROWS / 2 - 1);
    const float* srcA = (isK ? K : Q) + (size_t)(2 * pr) * HID;
    const float* srcB = srcA + HID;
    __half* dstA = (isK ? g_kf : g_qf) + (size_t)(2 * pr) * KD;
    __half* dstB = dstA + KD;

#pragma unroll
    for (int i = t; i < 768; i += 256)
        stw[i] = g_tw[i];

    {
        const float4 fa = ((const float4*)srcA)[t];
        const float4 fb = ((const float4*)srcB)[t];
        sd[FPAD(4 * t + 0)] = make_float2(fa.x, fb.x);
        sd[FPAD(4 * t + 1)] = make_float2(fa.y, fb.y);
        sd[FPAD(4 * t + 2)] = make_float2(fa.z, fb.z);
        sd[FPAD(4 * t + 3)] = make_float2(fa.w, fb.w);
    }
    __syncthreads();

#pragma unroll
    for (int st = 0; st < 5; st++) {
        const int qlog = 8 - 2 * st;
        const int q    = 1 << qlog;
        const int j    = t & (q - 1);
        const int sub  = t >> qlog;
        const int base = (sub << (qlog + 2)) | j;
        const int tw   = j << (2 * st);

        const float2 x0 = sd[FPAD(base)];
        const float2 x1 = sd[FPAD(base + q)];
        const float2 x2 = sd[FPAD(base + 2 * q)];
        const float2 x3 = sd[FPAD(base + 3 * q)];

        const float b0r = x0.x + x2.x, b0i = x0.y + x2.y;
        const float b1r = x1.x + x3.x, b1i = x1.y + x3.y;
        const float b2r = x0.x - x2.x, b2i = x0.y - x2.y;
        const float b3r = x1.x - x3.x, b3i = x1.y - x3.y;

        float y0r = b0r + b1r, y0i = b0i + b1i;
        float y1r = b2r + b3i, y1i = b2i - b3r;
        float y2r = b0r - b1r, y2i = b0i - b1i;
        float y3r = b2r - b3i, y3i = b2i + b3r;

        if (st < 4) {
            const float2 w1 = stw[tw];
            const float2 w2 = stw[2 * tw];
            const float2 w3 = stw[3 * tw];
            float r;
            r   = y1r * w1.x - y1i * w1.y;
            y1i = y1r * w1.y + y1i * w1.x;  y1r = r;
            r   = y2r * w2.x - y2i * w2.y;
            y2i = y2r * w2.y + y2i * w2.x;  y2r = r;
            r   = y3r * w3.x - y3i * w3.y;
            y3i = y3r * w3.y + y3i * w3.x;  y3r = r;
        }

        sd[FPAD(base)]         = make_float2(y0r, y0i);
        sd[FPAD(base + q)]     = make_float2(y1r, y1i);
        sd[FPAD(base + 2 * q)] = make_float2(y2r, y2i);
        sd[FPAD(base + 3 * q)] = make_float2(y3r, y3i);
        __syncthreads();
    }

    for (int k = t; k < NFREQ; k += 256) {
        const int kb  = (1024 - k) & 1023;
        const int ra  = __brev((unsigned)k)  >> 22;
        const int rb  = __brev((unsigned)kb) >> 22;
        const int pa  = ((ra & 0x155) << 1) | ((ra & 0x2AA) >> 1);
        const int pb  = ((rb & 0x155) << 1) | ((rb & 0x2AA) >> 1);
        const float2 za = sd[FPAD(pa)];
        const float2 zb = sd[FPAD(pb)];

        const float ar = za.x + zb.x;
        const float ai = za.y - zb.y;
        const float br = za.y + zb.y;
        const float bi = zb.x - za.x;

        {
            const float m2 = ar * ar + ai * ai;
            float cc = 1.0f, ss = 0.0f;
            if (m2 > 0.0f) {
                const float inv = rsqrtf(m2);
                cc = ar * inv;
                ss = ai * inv;
            }
            dstA[k] = __float2half(cc);
            if (k >= 1 && k < 512) dstA[512 + k] = __float2half(ss);
        }
        {
            const float m2 = br * br + bi * bi;
            float cc = 1.0f, ss = 0.0f;
            if (m2 > 0.0f) {
                const float inv = rsqrtf(m2);
                cc = br * inv;
                ss = bi * inv;
            }
            dstB[k] = __float2half(cc);
            if (k >= 1 && k < 512) dstB[512 + k] = __float2half(ss);
        }
    }
}

// ===========================================================================
// Kernel 2: V [b][j][h] fp32 -> g_vt [b][h][j] fp16.
// ===========================================================================
__global__ void vtrans_kernel(const float* __restrict__ V)
{
    __shared__ float s[32][65];                // [h][j]
    const int b  = blockIdx.z;
    const int h0 = blockIdx.x * 32;
    const int j0 = blockIdx.y * 64;
    const int tx = threadIdx.x, ty = threadIdx.y;   // 32 x 8

    const float* src = V + ((size_t)b * SEQ + j0) * HID + h0;
#pragma unroll
    for (int jj = ty; jj < 64; jj += 8)
        s[tx][jj] = src[(size_t)jj * HID + tx];
    __syncthreads();

    __half* dst = g_vt + ((size_t)b * HID + h0) * SEQ + j0;
#pragma unroll
    for (int hh = ty; hh < 32; hh += 8) {
        const float v0 = s[hh][2 * tx];
        const float v1 = s[hh][2 * tx + 1];
        *(__half2*)(dst + (size_t)hh * SEQ + 2 * tx) = __floats2half2_rn(v0, v1);
    }
}

// ===========================================================================
// Kernel 3/5: WARP-SPECIALIZED pipelined HMMA NT GEMM, BK=64 chunks.
// 128x128 CTA tile; warps 0-3 consumers (64x64, 2x2), warps 4-5 producers.
// 3-stage ring, 128B XOR-swizzled smem rows, mbarrier handoff.
// MODE 0: fp16 ACC per chunk (full-rate HMMA), fp32 promote between chunks;
//         epilogue g_wh = fp16 exp(acc/513 + 1). occupancy 1 (reg budget).
// MODE 1: fp32 ACC; out = (diag(1/rowsum).exp).V, row scale in epilogue.
// ===========================================================================
#define TILE_B   (128 * 128)                 // 16384 B per operand tile
#define STG_B    (2 * TILE_B)                // 32768 per stage
#define NSTAGE   3
#define CTRL_B   1024
#define GEMM_SMEM (CTRL_B + NSTAGE * STG_B)  // 99328

template <int MODE>
__global__ void __launch_bounds__(192, (MODE == 0) ? 1 : 2)
gemm_hmma(float* __restrict__ Dbase)
{
    constexpr int  KT  = (MODE == 0) ? KD : SEQ;
    constexpr int  LDA = (MODE == 0) ? KD : SEQ;
    constexpr int  LDB = (MODE == 0) ? KD : SEQ;
    constexpr long long ABS = (MODE == 0) ? (long long)SEQ * KD : (long long)SEQ * SEQ;
    constexpr long long BBS = (MODE == 0) ? (long long)SEQ * KD : (long long)HID * SEQ;
    constexpr int  LDD = (MODE == 0) ? SEQ : HID;
    constexpr long long DBS = (long long)SEQ * LDD;
    constexpr int  NC  = KT / 64;

    extern __shared__ __align__(256) char smem[];
    const uint32_t sb = smem_u32(smem);
    // mbarriers: full[s] = sb + 16s, empty[s] = sb + 16s + 8

    const int tid  = threadIdx.x;            // 192
    const int warp = tid >> 5;               // 0..5
    const int lane = tid & 31;
    const int m0 = blockIdx.x * 128;
    const int n0 = blockIdx.y * 128;
    const int bz = blockIdx.z;

    const __half* A = ((MODE == 0) ? g_qf : g_wh) + (long long)bz * ABS + (long long)m0 * LDA;
    const __half* B = ((MODE == 0) ? g_kf : g_vt) + (long long)bz * BBS + (long long)n0 * LDB;

    if (tid == 0) {
#pragma unroll
        for (int s = 0; s < NSTAGE; s++) {
            MBARRIER_INIT(sb + 16 * s,     64); // full: 64 producer lanes
            MBARRIER_INIT(sb + 16 * s + 8, 4);  // empty: 4 consumer warps
        }
    }
    __syncthreads();

    if (warp >= 4) {
        // ------------------- producer: warp4 -> A, warp5 -> B -------------
        const __half* src = (warp == 4) ? A : B;
        const int     ld  = (warp == 4) ? LDA : LDB;
        const uint32_t tb0 = sb + CTRL_B + ((warp == 4) ? 0u : (uint32_t)TILE_B);
        int pph = 1;
#pragma unroll 1
        for (int c = 0; c < NC; c++) {
            const int st = (c % NSTAGE);
            MBARRIER_WAIT_PARITY(sb + 16 * st + 8, pph);
            const uint32_t tb = tb0 + st * STG_B;
            const int k0 = c * 64;
#pragma unroll
            for (int j = 0; j < 32; j++) {          // 1024 cp16 per tile / 32 lanes
                const int idx = lane + j * 32;
                const int row = idx >> 3;            // 0..127
                const int seg = idx & 7;             // 16B seg in 128B row
                const uint32_t off = (uint32_t)((row << 7) | (seg << 4));
                cp16(tb + SWZ(off), src + (long long)row * ld + k0 + seg * 8);
            }
            CPASYNC_MBAR_ARRIVE_NOINC(sb + 16 * st);
            if (st == NSTAGE - 1) pph ^= 1;
        }
    } else {
        // ------------------- consumer: 2x2 warps, 64x64 tiles --------------
        const int wm = warp & 1;
        const int wn = warp >> 1;
        const int lr = lane & 15;
        const int lc = lane >> 4;

        float accf[4][8][4];
#pragma unroll
        for (int mt = 0; mt < 4; mt++)
#pragma unroll
            for (int nt = 0; nt < 8; nt++)
#pragma unroll
                for (int e = 0; e < 4; e++)
                    accf[mt][nt][e] = 0.0f;

        int cph = 0;
#pragma unroll 1
        for (int c = 0; c < NC; c++) {
            const int st = (c % NSTAGE);
            MBARRIER_WAIT_PARITY(sb + 16 * st, cph);
            const uint32_t ab = sb + CTRL_B + st * STG_B;
            const uint32_t bb = ab + TILE_B;

            if (MODE == 0) {
                // fp16 accumulators, zeroed per chunk
                uint32_t acch[4][8][2];
#pragma unroll
                for (int mt = 0; mt < 4; mt++)
#pragma unroll
                    for (int nt = 0; nt < 8; nt++) {
                        acch[mt][nt][0] = 0u;
                        acch[mt][nt][1] = 0u;
                    }
#pragma unroll
                for (int ks = 0; ks < 4; ks++) {
                    const uint32_t kb = (uint32_t)(ks * 32 + lc * 16);
                    uint32_t af[4][4];
                    uint32_t bf[4][4];
#pragma unroll
                    for (int mt = 0; mt < 4; mt++) {
                        const uint32_t off = (uint32_t)((wm * 64 + mt * 16 + lr) << 7) + kb;
                        LDSM4(af[mt], ab + SWZ(off));
                    }
#pragma unroll
                    for (int g = 0; g < 4; g++) {
                        const uint32_t off = (uint32_t)((wn * 64 + g * 16 + lr) << 7) + kb;
                        LDSM4(bf[g], bb + SWZ(off));
                    }
#pragma unroll
                    for (int mt = 0; mt < 4; mt++)
#pragma unroll
                        for (int g = 0; g < 4; g++) {
                            MMA16816H(acch[mt][2 * g],     af[mt][0], af[mt][1], af[mt][2], af[mt][3],
                                      bf[g][0], bf[g][2]);
                            MMA16816H(acch[mt][2 * g + 1], af[mt][0], af[mt][1], af[mt][2], af[mt][3],
                                      bf[g][1], bf[g][3]);
                        }
                }
                __syncwarp();
                if (elect_one())
                    MBARRIER_ARRIVE(sb + 16 * st + 8);
                // promote chunk partials to fp32
#pragma unroll
                for (int mt = 0; mt < 4; mt++)
#pragma unroll
                    for (int nt = 0; nt < 8; nt++) {
                        const float2 lo = __half22float2(*(__half2*)&acch[mt][nt][0]);
                        const float2 hi = __half22float2(*(__half2*)&acch[mt][nt][1]);
                        accf[mt][nt][0] += lo.x;
                        accf[mt][nt][1] += lo.y;
                        accf[mt][nt][2] += hi.x;
                        accf[mt][nt][3] += hi.y;
                    }
            } else {
#pragma unroll
                for (int ks = 0; ks < 4; ks++) {
                    const uint32_t kb = (uint32_t)(ks * 32 + lc * 16);
                    uint32_t af[4][4];
                    uint32_t bf[4][4];
#pragma unroll
                    for (int mt = 0; mt < 4; mt++) {
                        const uint32_t off = (uint32_t)((wm * 64 + mt * 16 + lr) << 7) + kb;
                        LDSM4(af[mt], ab + SWZ(off));
                    }
#pragma unroll
                    for (int g = 0; g < 4; g++) {
                        const uint32_t off = (uint32_t)((wn * 64 + g * 16 + lr) << 7) + kb;
                        LDSM4(bf[g], bb + SWZ(off));
                    }
#pragma unroll
                    for (int mt = 0; mt < 4; mt++)
#pragma unroll
                        for (int g = 0; g < 4; g++) {
                            MMA16816(accf[mt][2 * g],     af[mt][0], af[mt][1], af[mt][2], af[mt][3],
                                     bf[g][0], bf[g][2]);
                            MMA16816(accf[mt][2 * g + 1], af[mt][0], af[mt][1], af[mt][2], af[mt][3],
                                     bf[g][1], bf[g][3]);
                        }
                }
                __syncwarp();
                if (elect_one())
                    MBARRIER_ARRIVE(sb + 16 * st + 8);
            }
            if (st == NSTAGE - 1) cph ^= 1;
        }

        // Epilogue
        const int tr = lane >> 2;
        const int tc = (lane & 3) * 2;
        const int mbase = m0 + wm * 64;
        const int nbase = n0 + wn * 64;
        if (MODE == 0) {
            // fp16 exp(acc/513 + 1) -> g_wh
            __half* Dh = g_wh + (long long)bz * SEQ * SEQ;
            const float s = 1.0f / 513.0f;
#pragma unroll
            for (int mt = 0; mt < 4; mt++)
#pragma unroll
                for (int nt = 0; nt < 8; nt++) {
                    const float e0 = __expf(accf[mt][nt][0] * s + 1.0f);
                    const float e1 = __expf(accf[mt][nt][1] * s + 1.0f);
                    const float e2 = __expf(accf[mt][nt][2] * s + 1.0f);
                    const float e3 = __expf(accf[mt][nt][3] * s + 1.0f);
                    const int row = mbase + mt * 16 + tr;
                    const int col = nbase + nt * 8 + tc;
                    *(__half2*)(Dh + (long long)row * SEQ + col)       = __floats2half2_rn(e0, e1);
                    *(__half2*)(Dh + (long long)(row + 8) * SEQ + col) = __floats2half2_rn(e2, e3);
                }
        } else {
            float* D = Dbase + (long long)bz * DBS;
#pragma unroll
            for (int mt = 0; mt < 4; mt++) {
                const int row = mbase + mt * 16 + tr;
                const float ia = g_rsum[bz * SEQ + row];
                const float ib = g_rsum[bz * SEQ + row + 8];
#pragma unroll
                for (int nt = 0; nt < 8; nt++) {
                    const int col = nbase + nt * 8 + tc;
                    *(float2*)(D + (long long)row * LDD + col) =
                        make_float2(accf[mt][nt][0] * ia, accf[mt][nt][1] * ia);
                    *(float2*)(D + (long long)(row + 8) * LDD + col) =
                        make_float2(accf[mt][nt][2] * ib, accf[mt][nt][3] * ib);
                }
            }
        }
    }
}

// ===========================================================================
// Kernel 4: rowsum — reads fp16 exp from g_wh, writes inv rowsum to g_rsum
// and fp32 normalized weights to W. (No max needed: scores in [0,2].)
// ===========================================================================
__global__ void rowsum_kernel(float* __restrict__ W)
{
    __shared__ float ssum[8];
    const size_t row = blockIdx.x;
    const __half2* ph2 = (const __half2*)(g_wh + row * SEQ);
    float2* p2 = (float2*)(W + row * SEQ);
    const int t = threadIdx.x;

    float2 v[4];
    float s = 0.0f;
#pragma unroll
    for (int i = 0; i < 4; i++) {
        v[i] = __half22float2(ph2[t + 256 * i]);
        s += v[i].x + v[i].y;
    }
#pragma unroll
    for (int o = 16; o; o >>= 1) s += __shfl_xor_sync(0xffffffffu, s, o);
    if ((t & 31) == 0) ssum[t >> 5] = s;
    __syncthreads();
    s = ssum[0];
#pragma unroll
    for (int i = 1; i < 8; i++) s += ssum[i];
    const float inv = 1.0f / s;
    if (t == 0) g_rsum[row] = inv;

#pragma unroll
    for (int i = 0; i < 4; i++)
        p2[t + 256 * i] = make_float2(v[i].x * inv, v[i].y * inv);
}

// ===========================================================================
// Launch: out = [output (B*S*H fp32) | weights (B*S*S fp32)]
// ===========================================================================
extern "C" void kernel_launch(void* const* d_in, const int* in_sizes, int n_in,
                              void* d_out, int out_size)
{
    const float* Q = (const float*)d_in[0];
    const float* K = (const float*)d_in[1];
    const float* V = (const float*)d_in[2];
    float* out     = (float*)d_out;
    float* weights = out + (size_t)BATCH * SEQ * HID;

    cudaFuncSetAttribute(gemm_hmma<0>, cudaFuncAttributeMaxDynamicSharedMemorySize, GEMM_SMEM);
    cudaFuncSetAttribute(gemm_hmma<1>, cudaFuncAttributeMaxDynamicSharedMemorySize, GEMM_SMEM);

    // 0) twiddle table (once per launch; tiny)
    twiddle_init_kernel<<<3, 256>>>();

    // 1) phase features for Q and K (two rows per block)
    fft_phase_kernel<<<ROWS, 256>>>(Q, K);

    // 2) V -> fp16 transposed [b][h][j]
    {
        dim3 grid(HID / 32, SEQ / 64, BATCH);
        vtrans_kernel<<<grid, dim3(32, 8)>>>(V);
    }

    // 3) g_wh = fp16 exp(QF.KF^T/513 + 1)  (fp16-acc chunks)
    {
        dim3 grid(SEQ / 128, SEQ / 128, BATCH);
        gemm_hmma<0><<<grid, 192, GEMM_SMEM>>>(weights);
    }

    // 4) rowsum: inv sums to g_rsum + fp32 weights output
    rowsum_kernel<<<ROWS, 256>>>(weights);

    // 5) output = (diag(inv) . exp) @ V  (row scale in epilogue)
    {
        dim3 grid(SEQ / 128, HID / 128, BATCH);
        gemm_hmma<1><<<grid, 192, GEMM_SMEM>>>(out);
    }
}

// round 15
// speedup vs baseline: 1.0622x; 1.0622x over previous
#include <cuda_runtime.h>
#include <cuda_fp16.h>
#include <stdint.h>

// Problem constants
#define BATCH 4
#define SEQ   2048
#define HID   1024
#define NFREQ 513           // H/2 + 1
#define KD    1024          // 513 cos + 511 sin (sin0 == sin512 == 0 exactly)
#define ROWS  (BATCH * SEQ) // 8192

// Scratch (static __device__ — no allocations allowed)
__device__ __align__(256) __half g_qf[(size_t)ROWS * KD];         // Q phase features
__device__ __align__(256) __half g_kf[(size_t)ROWS * KD];         // K phase features
__device__ __align__(256) __half g_wh[(size_t)ROWS * SEQ];        // fp16 exp(scores)
__device__ __align__(256) __half g_vt[(size_t)BATCH * HID * SEQ]; // V^T [b][h][j] fp16
__device__ float  g_rsum[ROWS];                                   // 1/rowsum per row
__device__ float2 g_tw[768];                                      // W_1024^t, t=0..767

// ===========================================================================
// PTX helpers
// ===========================================================================
__device__ __forceinline__ uint32_t smem_u32(const void* p) {
    uint32_t a;
    asm("{ .reg .u64 t; cvta.to.shared.u64 t, %1; cvt.u32.u64 %0, t; }"
        : "=r"(a) : "l"(p));
    return a;
}
__device__ __forceinline__ uint32_t elect_one() {
    uint32_t p;
    asm volatile(
        "{\n\t.reg .pred p;\n\telect.sync _|p, 0xFFFFFFFF;\n\t"
        "selp.b32 %0, 1, 0, p;\n\t}" : "=r"(p));
    return p;
}
__device__ __forceinline__ void cp16(uint32_t dst, const void* src) {
    asm volatile("cp.async.cg.shared.global [%0], [%1], 16;" :: "r"(dst), "l"(src));
}

#define MBARRIER_INIT(addr, cnt) \
    asm volatile("mbarrier.init.shared.b64 [%0], %1;" :: "r"((uint32_t)(addr)), "r"((uint32_t)(cnt)) : "memory")
#define MBARRIER_ARRIVE(addr) \
    asm volatile("mbarrier.arrive.shared.b64 _, [%0];" :: "r"((uint32_t)(addr)) : "memory")
#define CPASYNC_MBAR_ARRIVE_NOINC(addr) \
    asm volatile("cp.async.mbarrier.arrive.noinc.shared.b64 [%0];" :: "r"((uint32_t)(addr)) : "memory")

#define MBARRIER_WAIT_PARITY(mbar_smem_addr, phase_parity) do { \
    uint32_t _mbar = (uint32_t)(mbar_smem_addr); \
    uint32_t _parity = (uint32_t)(phase_parity); \
    uint32_t _done; \
    asm volatile( \
        "{\n\t.reg .pred p;\n\t" \
        "mbarrier.try_wait.parity.acquire.cta.shared::cta.b64 p, [%1], %2;\n\t" \
        "selp.b32 %0, 1, 0, p;\n\t}" \
        : "=r"(_done) : "r"(_mbar), "r"(_parity) : "memory"); \
    if (!_done) { \
        asm volatile( \
            "{\n\t.reg .pred P1;\n\t" \
            "WAIT_LOOP_%=:\n\t" \
            "mbarrier.try_wait.parity.acquire.cta.shared::cta.b64 P1, [%0], %1, 0x989680;\n\t" \
            "@P1 bra.uni WAIT_DONE_%=;\n\t" \
            "bra.uni WAIT_LOOP_%=;\n\t" \
            "WAIT_DONE_%=:\n\t}" \
            :: "r"(_mbar), "r"(_parity) : "memory"); \
    } \
} while (0)

#define LDSM4(r, a)                                                          \
    asm volatile("ldmatrix.sync.aligned.m8n8.x4.shared.b16 {%0,%1,%2,%3}, [%4];" \
                 : "=r"((r)[0]), "=r"((r)[1]), "=r"((r)[2]), "=r"((r)[3])    \
                 : "r"(a))

#define MMA16816(d, a0, a1, a2, a3, b0, b1)                                  \
    asm volatile(                                                            \
        "mma.sync.aligned.m16n8k16.row.col.f32.f16.f16.f32 "                 \
        "{%0,%1,%2,%3}, {%4,%5,%6,%7}, {%8,%9}, {%0,%1,%2,%3};"              \
        : "+f"((d)[0]), "+f"((d)[1]), "+f"((d)[2]), "+f"((d)[3])             \
        : "r"(a0), "r"(a1), "r"(a2), "r"(a3), "r"(b0), "r"(b1))

// 128B-row XOR swizzle: rows 0..127, bits[6:4] ^= row&7
#define SWZ(o) ((o) ^ ((((o) >> 7) & 7) << 4))

// ===========================================================================
// Kernel 0: one-time twiddle table W_1024^t = exp(-2*pi*i*t/1024), t<768
// ===========================================================================
__global__ void twiddle_init_kernel()
{
    const int t = blockIdx.x * 256 + threadIdx.x;
    if (t < 768) {
        float s, c;
        sincosf(-6.283185307179586f * (float)t * (1.0f / 1024.0f), &s, &c);
        g_tw[t] = make_float2(c, s);
    }
}

// ===========================================================================
// Kernel 1: two real rows per block packed into ONE complex FFT-1024
// (radix-4 DIF, 5 stages), untangle at readout.
// Feature layout: dst[k] = cos_k (k=0..512), dst[512+k] = sin_k (k=1..511).
// sin_0 = sin_512 = 0 exactly -> dropped; KD = 1024 exactly.
// ===========================================================================
#define FPAD(i) ((i) + ((i) >> 4))

__global__ void fft_phase_kernel(const float* __restrict__ Q,
                                 const float* __restrict__ K)
{
    __shared__ float2 sd[1024 + 64];
    __shared__ float2 stw[768];

    const int t = threadIdx.x;                 // 256 threads
    const bool isK = blockIdx.x >= (ROWS / 2);
    const int pr = blockIdx.x & (ROWS / 2 - 1);
    const float* srcA = (isK ? K : Q) + (size_t)(2 * pr) * HID;
    const float* srcB = srcA + HID;
    __half* dstA = (isK ? g_kf : g_qf) + (size_t)(2 * pr) * KD;
    __half* dstB = dstA + KD;

#pragma unroll
    for (int i = t; i < 768; i += 256)
        stw[i] = g_tw[i];

    {
        const float4 fa = ((const float4*)srcA)[t];
        const float4 fb = ((const float4*)srcB)[t];
        sd[FPAD(4 * t + 0)] = make_float2(fa.x, fb.x);
        sd[FPAD(4 * t + 1)] = make_float2(fa.y, fb.y);
        sd[FPAD(4 * t + 2)] = make_float2(fa.z, fb.z);
        sd[FPAD(4 * t + 3)] = make_float2(fa.w, fb.w);
    }
    __syncthreads();

#pragma unroll
    for (int st = 0; st < 5; st++) {
        const int qlog = 8 - 2 * st;
        const int q    = 1 << qlog;
        const int j    = t & (q - 1);
        const int sub  = t >> qlog;
        const int base = (sub << (qlog + 2)) | j;
        const int tw   = j << (2 * st);

        const float2 x0 = sd[FPAD(base)];
        const float2 x1 = sd[FPAD(base + q)];
        const float2 x2 = sd[FPAD(base + 2 * q)];
        const float2 x3 = sd[FPAD(base + 3 * q)];

        const float b0r = x0.x + x2.x, b0i = x0.y + x2.y;
        const float b1r = x1.x + x3.x, b1i = x1.y + x3.y;
        const float b2r = x0.x - x2.x, b2i = x0.y - x2.y;
        const float b3r = x1.x - x3.x, b3i = x1.y - x3.y;

        float y0r = b0r + b1r, y0i = b0i + b1i;
        float y1r = b2r + b3i, y1i = b2i - b3r;
        float y2r = b0r - b1r, y2i = b0i - b1i;
        float y3r = b2r - b3i, y3i = b2i + b3r;

        if (st < 4) {
            const float2 w1 = stw[tw];
            const float2 w2 = stw[2 * tw];
            const float2 w3 = stw[3 * tw];
            float r;
            r   = y1r * w1.x - y1i * w1.y;
            y1i = y1r * w1.y + y1i * w1.x;  y1r = r;
            r   = y2r * w2.x - y2i * w2.y;
            y2i = y2r * w2.y + y2i * w2.x;  y2r = r;
            r   = y3r * w3.x - y3i * w3.y;
            y3i = y3r * w3.y + y3i * w3.x;  y3r = r;
        }

        sd[FPAD(base)]         = make_float2(y0r, y0i);
        sd[FPAD(base + q)]     = make_float2(y1r, y1i);
        sd[FPAD(base + 2 * q)] = make_float2(y2r, y2i);
        sd[FPAD(base + 3 * q)] = make_float2(y3r, y3i);
        __syncthreads();
    }

    for (int k = t; k < NFREQ; k += 256) {
        const int kb  = (1024 - k) & 1023;
        const int ra  = __brev((unsigned)k)  >> 22;
        const int rb  = __brev((unsigned)kb) >> 22;
        const int pa  = ((ra & 0x155) << 1) | ((ra & 0x2AA) >> 1);
        const int pb  = ((rb & 0x155) << 1) | ((rb & 0x2AA) >> 1);
        const float2 za = sd[FPAD(pa)];
        const float2 zb = sd[FPAD(pb)];

        const float ar = za.x + zb.x;
        const float ai = za.y - zb.y;
        const float br = za.y + zb.y;
        const float bi = zb.x - za.x;

        {
            const float m2 = ar * ar + ai * ai;
            float cc = 1.0f, ss = 0.0f;
            if (m2 > 0.0f) {
                const float inv = rsqrtf(m2);
                cc = ar * inv;
                ss = ai * inv;
            }
            dstA[k] = __float2half(cc);
            if (k >= 1 && k < 512) dstA[512 + k] = __float2half(ss);
        }
        {
            const float m2 = br * br + bi * bi;
            float cc = 1.0f, ss = 0.0f;
            if (m2 > 0.0f) {
                const float inv = rsqrtf(m2);
                cc = br * inv;
                ss = bi * inv;
            }
            dstB[k] = __float2half(cc);
            if (k >= 1 && k < 512) dstB[512 + k] = __float2half(ss);
        }
    }
}

// ===========================================================================
// Kernel 2: V [b][j][h] fp32 -> g_vt [b][h][j] fp16.
// ===========================================================================
__global__ void vtrans_kernel(const float* __restrict__ V)
{
    __shared__ float s[32][65];                // [h][j]
    const int b  = blockIdx.z;
    const int h0 = blockIdx.x * 32;
    const int j0 = blockIdx.y * 64;
    const int tx = threadIdx.x, ty = threadIdx.y;   // 32 x 8

    const float* src = V + ((size_t)b * SEQ + j0) * HID + h0;
#pragma unroll
    for (int jj = ty; jj < 64; jj += 8)
        s[tx][jj] = src[(size_t)jj * HID + tx];
    __syncthreads();

    __half* dst = g_vt + ((size_t)b * HID + h0) * SEQ + j0;
#pragma unroll
    for (int hh = ty; hh < 32; hh += 8) {
        const float v0 = s[hh][2 * tx];
        const float v1 = s[hh][2 * tx + 1];
        *(__half2*)(dst + (size_t)hh * SEQ + 2 * tx) = __floats2half2_rn(v0, v1);
    }
}

// ===========================================================================
// Kernel 3/5: WARP-SPECIALIZED pipelined HMMA NT GEMM, BK=64 chunks.
// 128x128 CTA tile; warps 0-3 consumers (64x64, 2x2), warps 4-5 producers.
// 3-stage ring, 128B XOR-swizzled smem rows, mbarrier handoff, fp32 acc.
// MODE 0: g_wh = fp16 exp(QF.KF^T/513 + 1).
// MODE 1: out = (diag(1/rowsum) . exp) . V  (row scale fused in epilogue).
// ===========================================================================
#define TILE_B   (128 * 128)                 // 16384 B per operand tile
#define STG_B    (2 * TILE_B)                // 32768 per stage
#define NSTAGE   3
#define CTRL_B   1024
#define GEMM_SMEM (CTRL_B + NSTAGE * STG_B)  // 99328 -> 2 CTAs/SM

template <int MODE>
__global__ void __launch_bounds__(192, 2) gemm_hmma(float* __restrict__ Dbase)
{
    constexpr int  KT  = (MODE == 0) ? KD : SEQ;
    constexpr int  LDA = (MODE == 0) ? KD : SEQ;
    constexpr int  LDB = (MODE == 0) ? KD : SEQ;
    constexpr long long ABS = (MODE == 0) ? (long long)SEQ * KD : (long long)SEQ * SEQ;
    constexpr long long BBS = (MODE == 0) ? (long long)SEQ * KD : (long long)HID * SEQ;
    constexpr int  LDD = (MODE == 0) ? SEQ : HID;
    constexpr long long DBS = (long long)SEQ * LDD;
    constexpr int  NC  = KT / 64;

    extern __shared__ __align__(256) char smem[];
    const uint32_t sb = smem_u32(smem);
    // mbarriers: full[s] = sb + 16s, empty[s] = sb + 16s + 8

    const int tid  = threadIdx.x;            // 192
    const int warp = tid >> 5;               // 0..5
    const int lane = tid & 31;
    const int m0 = blockIdx.x * 128;
    const int n0 = blockIdx.y * 128;
    const int bz = blockIdx.z;

    const __half* A = ((MODE == 0) ? g_qf : g_wh) + (long long)bz * ABS + (long long)m0 * LDA;
    const __half* B = ((MODE == 0) ? g_kf : g_vt) + (long long)bz * BBS + (long long)n0 * LDB;

    if (tid == 0) {
#pragma unroll
        for (int s = 0; s < NSTAGE; s++) {
            MBARRIER_INIT(sb + 16 * s,     64); // full: 64 producer lanes
            MBARRIER_INIT(sb + 16 * s + 8, 4);  // empty: 4 consumer warps
        }
    }
    __syncthreads();

    if (warp >= 4) {
        // ------------------- producer: warp4 -> A, warp5 -> B -------------
        const __half* src = (warp == 4) ? A : B;
        const int     ld  = (warp == 4) ? LDA : LDB;
        const uint32_t tb0 = sb + CTRL_B + ((warp == 4) ? 0u : (uint32_t)TILE_B);
        int pph = 1;
#pragma unroll 1
        for (int c = 0; c < NC; c++) {
            const int st = (c % NSTAGE);
            MBARRIER_WAIT_PARITY(sb + 16 * st + 8, pph);
            const uint32_t tb = tb0 + st * STG_B;
            const int k0 = c * 64;
#pragma unroll
            for (int j = 0; j < 32; j++) {          // 1024 cp16 per tile / 32 lanes
                const int idx = lane + j * 32;
                const int row = idx >> 3;            // 0..127
                const int seg = idx & 7;             // 16B seg in 128B row
                const uint32_t off = (uint32_t)((row << 7) | (seg << 4));
                cp16(tb + SWZ(off), src + (long long)row * ld + k0 + seg * 8);
            }
            CPASYNC_MBAR_ARRIVE_NOINC(sb + 16 * st);
            if (st == NSTAGE - 1) pph ^= 1;
        }
    } else {
        // ------------------- consumer: 2x2 warps, 64x64 tiles --------------
        const int wm = warp & 1;
        const int wn = warp >> 1;
        const int lr = lane & 15;
        const int lc = lane >> 4;

        float acc[4][8][4];
#pragma unroll
        for (int mt = 0; mt < 4; mt++)
#pragma unroll
            for (int nt = 0; nt < 8; nt++)
#pragma unroll
                for (int e = 0; e < 4; e++)
                    acc[mt][nt][e] = 0.0f;

        int cph = 0;
#pragma unroll 1
        for (int c = 0; c < NC; c++) {
            const int st = (c % NSTAGE);
            MBARRIER_WAIT_PARITY(sb + 16 * st, cph);
            const uint32_t ab = sb + CTRL_B + st * STG_B;
            const uint32_t bb = ab + TILE_B;
#pragma unroll
            for (int ks = 0; ks < 4; ks++) {
                const uint32_t kb = (uint32_t)(ks * 32 + lc * 16);
                uint32_t af[4][4];
                uint32_t bf[4][4];
#pragma unroll
                for (int mt = 0; mt < 4; mt++) {
                    const uint32_t off = (uint32_t)((wm * 64 + mt * 16 + lr) << 7) + kb;
                    LDSM4(af[mt], ab + SWZ(off));
                }
#pragma unroll
                for (int g = 0; g < 4; g++) {
                    const uint32_t off = (uint32_t)((wn * 64 + g * 16 + lr) << 7) + kb;
                    LDSM4(bf[g], bb + SWZ(off));
                }
#pragma unroll
                for (int mt = 0; mt < 4; mt++)
#pragma unroll
                    for (int g = 0; g < 4; g++) {
                        MMA16816(acc[mt][2 * g],     af[mt][0], af[mt][1], af[mt][2], af[mt][3],
                                 bf[g][0], bf[g][2]);
                        MMA16816(acc[mt][2 * g + 1], af[mt][0], af[mt][1], af[mt][2], af[mt][3],
                                 bf[g][1], bf[g][3]);
                    }
            }
            __syncwarp();
            if (elect_one())
                MBARRIER_ARRIVE(sb + 16 * st + 8);
            if (st == NSTAGE - 1) cph ^= 1;
        }

        // Epilogue
        const int tr = lane >> 2;
        const int tc = (lane & 3) * 2;
        const int mbase = m0 + wm * 64;
        const int nbase = n0 + wn * 64;
        if (MODE == 0) {
            // fp16 exp(acc/513 + 1) -> g_wh
            __half* Dh = g_wh + (long long)bz * SEQ * SEQ;
            const float s = 1.0f / 513.0f;
#pragma unroll
            for (int mt = 0; mt < 4; mt++)
#pragma unroll
                for (int nt = 0; nt < 8; nt++) {
                    const float e0 = __expf(acc[mt][nt][0] * s + 1.0f);
                    const float e1 = __expf(acc[mt][nt][1] * s + 1.0f);
                    const float e2 = __expf(acc[mt][nt][2] * s + 1.0f);
                    const float e3 = __expf(acc[mt][nt][3] * s + 1.0f);
                    const int row = mbase + mt * 16 + tr;
                    const int col = nbase + nt * 8 + tc;
                    *(__half2*)(Dh + (long long)row * SEQ + col)       = __floats2half2_rn(e0, e1);
                    *(__half2*)(Dh + (long long)(row + 8) * SEQ + col) = __floats2half2_rn(e2, e3);
                }
        } else {
            float* D = Dbase + (long long)bz * DBS;
#pragma unroll
            for (int mt = 0; mt < 4; mt++) {
                const int row = mbase + mt * 16 + tr;
                const float ia = g_rsum[bz * SEQ + row];
                const float ib = g_rsum[bz * SEQ + row + 8];
#pragma unroll
                for (int nt = 0; nt < 8; nt++) {
                    const int col = nbase + nt * 8 + tc;
                    *(float2*)(D + (long long)row * LDD + col) =
                        make_float2(acc[mt][nt][0] * ia, acc[mt][nt][1] * ia);
                    *(float2*)(D + (long long)(row + 8) * LDD + col) =
                        make_float2(acc[mt][nt][2] * ib, acc[mt][nt][3] * ib);
                }
            }
        }
    }
}

// ===========================================================================
// Kernel 4: rowsum — reads fp16 exp from g_wh, writes inv rowsum to g_rsum
// and fp32 normalized weights to W. (No max needed: scores in [0,2].)
// ===========================================================================
__global__ void rowsum_kernel(float* __restrict__ W)
{
    __shared__ float ssum[8];
    const size_t row = blockIdx.x;
    const __half2* ph2 = (const __half2*)(g_wh + row * SEQ);
    float2* p2 = (float2*)(W + row * SEQ);
    const int t = threadIdx.x;

    float2 v[4];
    float s = 0.0f;
#pragma unroll
    for (int i = 0; i < 4; i++) {
        v[i] = __half22float2(ph2[t + 256 * i]);
        s += v[i].x + v[i].y;
    }
#pragma unroll
    for (int o = 16; o; o >>= 1) s += __shfl_xor_sync(0xffffffffu, s, o);
    if ((t & 31) == 0) ssum[t >> 5] = s;
    __syncthreads();
    s = ssum[0];
#pragma unroll
    for (int i = 1; i < 8; i++) s += ssum[i];
    const float inv = 1.0f / s;
    if (t == 0) g_rsum[row] = inv;

#pragma unroll
    for (int i = 0; i < 4; i++)
        p2[t + 256 * i] = make_float2(v[i].x * inv, v[i].y * inv);
}

// ===========================================================================
// Launch: out = [output (B*S*H fp32) | weights (B*S*S fp32)]
// ===========================================================================
extern "C" void kernel_launch(void* const* d_in, const int* in_sizes, int n_in,
                              void* d_out, int out_size)
{
    const float* Q = (const float*)d_in[0];
    const float* K = (const float*)d_in[1];
    const float* V = (const float*)d_in[2];
    float* out     = (float*)d_out;
    float* weights = out + (size_t)BATCH * SEQ * HID;

    cudaFuncSetAttribute(gemm_hmma<0>, cudaFuncAttributeMaxDynamicSharedMemorySize, GEMM_SMEM);
    cudaFuncSetAttribute(gemm_hmma<1>, cudaFuncAttributeMaxDynamicSharedMemorySize, GEMM_SMEM);

    // 0) twiddle table (once per launch; tiny)
    twiddle_init_kernel<<<3, 256>>>();

    // 1) phase features for Q and K (two rows per block)
    fft_phase_kernel<<<ROWS, 256>>>(Q, K);

    // 2) V -> fp16 transposed [b][h][j]
    {
        dim3 grid(HID / 32, SEQ / 64, BATCH);
        vtrans_kernel<<<grid, dim3(32, 8)>>>(V);
    }

    // 3) g_wh = fp16 exp(QF.KF^T/513 + 1)
    {
        dim3 grid(SEQ / 128, SEQ / 128, BATCH);
        gemm_hmma<0><<<grid, 192, GEMM_SMEM>>>(weights);
    }

    // 4) rowsum: inv sums to g_rsum + fp32 weights output
    rowsum_kernel<<<ROWS, 256>>>(weights);

    // 5) output = (diag(inv) . exp) @ V  (row scale in epilogue)
    {
        dim3 grid(SEQ / 128, HID / 128, BATCH);
        gemm_hmma<1><<<grid, 192, GEMM_SMEM>>>(out);
    }
}

// round 16
// speedup vs baseline: 1.0669x; 1.0045x over previous
#include <cuda_runtime.h>
#include <cuda_fp16.h>
#include <stdint.h>

// Problem constants
#define BATCH 4
#define SEQ   2048
#define HID   1024
#define NFREQ 513           // H/2 + 1
#define KD    1024          // 513 cos + 511 sin (sin0 == sin512 == 0 exactly)
#define ROWS  (BATCH * SEQ) // 8192

// Scratch (static __device__ — no allocations allowed)
__device__ __align__(256) __half g_qf[(size_t)ROWS * KD];         // Q phase features
__device__ __align__(256) __half g_kf[(size_t)ROWS * KD];         // K phase features
__device__ __align__(256) __half g_wh[(size_t)ROWS * SEQ];        // fp16 exp(scores)
__device__ __align__(256) __half g_vt[(size_t)BATCH * HID * SEQ]; // V^T [b][h][j] fp16
__device__ float  g_rsum[ROWS];                                   // 1/rowsum per row
__device__ float2 g_tw[768];                                      // W_1024^t, t=0..767

// ===========================================================================
// PTX helpers
// ===========================================================================
__device__ __forceinline__ uint32_t smem_u32(const void* p) {
    uint32_t a;
    asm("{ .reg .u64 t; cvta.to.shared.u64 t, %1; cvt.u32.u64 %0, t; }"
        : "=r"(a) : "l"(p));
    return a;
}
__device__ __forceinline__ uint32_t elect_one() {
    uint32_t p;
    asm volatile(
        "{\n\t.reg .pred p;\n\telect.sync _|p, 0xFFFFFFFF;\n\t"
        "selp.b32 %0, 1, 0, p;\n\t}" : "=r"(p));
    return p;
}
__device__ __forceinline__ void cp16(uint32_t dst, const void* src) {
    asm volatile("cp.async.cg.shared.global [%0], [%1], 16;" :: "r"(dst), "l"(src));
}

#define MBARRIER_INIT(addr, cnt) \
    asm volatile("mbarrier.init.shared.b64 [%0], %1;" :: "r"((uint32_t)(addr)), "r"((uint32_t)(cnt)) : "memory")
#define MBARRIER_ARRIVE(addr) \
    asm volatile("mbarrier.arrive.shared.b64 _, [%0];" :: "r"((uint32_t)(addr)) : "memory")
#define CPASYNC_MBAR_ARRIVE_NOINC(addr) \
    asm volatile("cp.async.mbarrier.arrive.noinc.shared.b64 [%0];" :: "r"((uint32_t)(addr)) : "memory")

#define MBARRIER_WAIT_PARITY(mbar_smem_addr, phase_parity) do { \
    uint32_t _mbar = (uint32_t)(mbar_smem_addr); \
    uint32_t _parity = (uint32_t)(phase_parity); \
    uint32_t _done; \
    asm volatile( \
        "{\n\t.reg .pred p;\n\t" \
        "mbarrier.try_wait.parity.acquire.cta.shared::cta.b64 p, [%1], %2;\n\t" \
        "selp.b32 %0, 1, 0, p;\n\t}" \
        : "=r"(_done) : "r"(_mbar), "r"(_parity) : "memory"); \
    if (!_done) { \
        asm volatile( \
            "{\n\t.reg .pred P1;\n\t" \
            "WAIT_LOOP_%=:\n\t" \
            "mbarrier.try_wait.parity.acquire.cta.shared::cta.b64 P1, [%0], %1, 0x989680;\n\t" \
            "@P1 bra.uni WAIT_DONE_%=;\n\t" \
            "bra.uni WAIT_LOOP_%=;\n\t" \
            "WAIT_DONE_%=:\n\t}" \
            :: "r"(_mbar), "r"(_parity) : "memory"); \
    } \
} while (0)

#define LDSM4(r, a)                                                          \
    asm volatile("ldmatrix.sync.aligned.m8n8.x4.shared.b16 {%0,%1,%2,%3}, [%4];" \
                 : "=r"((r)[0]), "=r"((r)[1]), "=r"((r)[2]), "=r"((r)[3])    \
                 : "r"(a))

#define MMA16816(d, a0, a1, a2, a3, b0, b1)                                  \
    asm volatile(                                                            \
        "mma.sync.aligned.m16n8k16.row.col.f32.f16.f16.f32 "                 \
        "{%0,%1,%2,%3}, {%4,%5,%6,%7}, {%8,%9}, {%0,%1,%2,%3};"              \
        : "+f"((d)[0]), "+f"((d)[1]), "+f"((d)[2]), "+f"((d)[3])             \
        : "r"(a0), "r"(a1), "r"(a2), "r"(a3), "r"(b0), "r"(b1))

// 128B-row XOR swizzle: rows 0..127, bits[6:4] ^= row&7
#define SWZ(o) ((o) ^ ((((o) >> 7) & 7) << 4))

// ===========================================================================
// Kernel 0: one-time twiddle table W_1024^t = exp(-2*pi*i*t/1024), t<768
// ===========================================================================
__global__ void twiddle_init_kernel()
{
    const int t = blockIdx.x * 256 + threadIdx.x;
    if (t < 768) {
        float s, c;
        sincosf(-6.283185307179586f * (float)t * (1.0f / 1024.0f), &s, &c);
        g_tw[t] = make_float2(c, s);
    }
}

// ===========================================================================
// Kernel 1: two real rows per block packed into ONE complex FFT-1024
// (radix-4 DIF, 5 stages), untangle at readout.
// Feature layout: dst[k] = cos_k (k=0..512), dst[512+k] = sin_k (k=1..511).
// ===========================================================================
#define FPAD(i) ((i) + ((i) >> 4))

__global__ void fft_phase_kernel(const float* __restrict__ Q,
                                 const float* __restrict__ K)
{
    __shared__ float2 sd[1024 + 64];
    __shared__ float2 stw[768];

    const int t = threadIdx.x;                 // 256 threads
    const bool isK = blockIdx.x >= (ROWS / 2);
    const int pr = blockIdx.x & (ROWS / 2 - 1);
    const float* srcA = (isK ? K : Q) + (size_t)(2 * pr) * HID;
    const float* srcB = srcA + HID;
    __half* dstA = (isK ? g_kf : g_qf) + (size_t)(2 * pr) * KD;
    __half* dstB = dstA + KD;

#pragma unroll
    for (int i = t; i < 768; i += 256)
        stw[i] = g_tw[i];

    {
        const float4 fa = ((const float4*)srcA)[t];
        const float4 fb = ((const float4*)srcB)[t];
        sd[FPAD(4 * t + 0)] = make_float2(fa.x, fb.x);
        sd[FPAD(4 * t + 1)] = make_float2(fa.y, fb.y);
        sd[FPAD(4 * t + 2)] = make_float2(fa.z, fb.z);
        sd[FPAD(4 * t + 3)] = make_float2(fa.w, fb.w);
    }
    __syncthreads();

#pragma unroll
    for (int st = 0; st < 5; st++) {
        const int qlog = 8 - 2 * st;
        const int q    = 1 << qlog;
        const int j    = t & (q - 1);
        const int sub  = t >> qlog;
        const int base = (sub << (qlog + 2)) | j;
        const int tw   = j << (2 * st);

        const float2 x0 = sd[FPAD(base)];
        const float2 x1 = sd[FPAD(base + q)];
        const float2 x2 = sd[FPAD(base + 2 * q)];
        const float2 x3 = sd[FPAD(base + 3 * q)];

        const float b0r = x0.x + x2.x, b0i = x0.y + x2.y;
        const float b1r = x1.x + x3.x, b1i = x1.y + x3.y;
        const float b2r = x0.x - x2.x, b2i = x0.y - x2.y;
        const float b3r = x1.x - x3.x, b3i = x1.y - x3.y;

        float y0r = b0r + b1r, y0i = b0i + b1i;
        float y1r = b2r + b3i, y1i = b2i - b3r;
        float y2r = b0r - b1r, y2i = b0i - b1i;
        float y3r = b2r - b3i, y3i = b2i + b3r;

        if (st < 4) {
            const float2 w1 = stw[tw];
            const float2 w2 = stw[2 * tw];
            const float2 w3 = stw[3 * tw];
            float r;
            r   = y1r * w1.x - y1i * w1.y;
            y1i = y1r * w1.y + y1i * w1.x;  y1r = r;
            r   = y2r * w2.x - y2i * w2.y;
            y2i = y2r * w2.y + y2i * w2.x;  y2r = r;
            r   = y3r * w3.x - y3i * w3.y;
            y3i = y3r * w3.y + y3i * w3.x;  y3r = r;
        }

        sd[FPAD(base)]         = make_float2(y0r, y0i);
        sd[FPAD(base + q)]     = make_float2(y1r, y1i);
        sd[FPAD(base + 2 * q)] = make_float2(y2r, y2i);
        sd[FPAD(base + 3 * q)] = make_float2(y3r, y3i);
        __syncthreads();
    }

    for (int k = t; k < NFREQ; k += 256) {
        const int kb  = (1024 - k) & 1023;
        const int ra  = __brev((unsigned)k)  >> 22;
        const int rb  = __brev((unsigned)kb) >> 22;
        const int pa  = ((ra & 0x155) << 1) | ((ra & 0x2AA) >> 1);
        const int pb  = ((rb & 0x155) << 1) | ((rb & 0x2AA) >> 1);
        const float2 za = sd[FPAD(pa)];
        const float2 zb = sd[FPAD(pb)];

        const float ar = za.x + zb.x;
        const float ai = za.y - zb.y;
        const float br = za.y + zb.y;
        const float bi = zb.x - za.x;

        {
            const float m2 = ar * ar + ai * ai;
            float cc = 1.0f, ss = 0.0f;
            if (m2 > 0.0f) {
                const float inv = rsqrtf(m2);
                cc = ar * inv;
                ss = ai * inv;
            }
            dstA[k] = __float2half(cc);
            if (k >= 1 && k < 512) dstA[512 + k] = __float2half(ss);
        }
        {
            const float m2 = br * br + bi * bi;
            float cc = 1.0f, ss = 0.0f;
            if (m2 > 0.0f) {
                const float inv = rsqrtf(m2);
                cc = br * inv;
                ss = bi * inv;
            }
            dstB[k] = __float2half(cc);
            if (k >= 1 && k < 512) dstB[512 + k] = __float2half(ss);
        }
    }
}

// ===========================================================================
// Kernel 2: V [b][j][h] fp32 -> g_vt [b][h][j] fp16.
// ===========================================================================
__global__ void vtrans_kernel(const float* __restrict__ V)
{
    __shared__ float s[32][65];                // [h][j]
    const int b  = blockIdx.z;
    const int h0 = blockIdx.x * 32;
    const int j0 = blockIdx.y * 64;
    const int tx = threadIdx.x, ty = threadIdx.y;   // 32 x 8

    const float* src = V + ((size_t)b * SEQ + j0) * HID + h0;
#pragma unroll
    for (int jj = ty; jj < 64; jj += 8)
        s[tx][jj] = src[(size_t)jj * HID + tx];
    __syncthreads();

    __half* dst = g_vt + ((size_t)b * HID + h0) * SEQ + j0;
#pragma unroll
    for (int hh = ty; hh < 32; hh += 8) {
        const float v0 = s[hh][2 * tx];
        const float v1 = s[hh][2 * tx + 1];
        *(__half2*)(dst + (size_t)hh * SEQ + 2 * tx) = __floats2half2_rn(v0, v1);
    }
}

// ===========================================================================
// Kernel 3/5: WARP-SPECIALIZED pipelined HMMA NT GEMM, BK=64 chunks.
// 128x128 CTA tile; warps 0-3 consumers (64x64, 2x2), warps 4-5 producers.
// 3-stage ring, 128B XOR-swizzled smem rows, mbarrier handoff, fp32 acc.
// MODE 0: g_wh = fp16 exp(QF.KF^T/513 + 1).
// MODE 1: out = (diag(1/rowsum) . exp) . V  (row scale fused in epilogue);
//         producer warps ALSO stream the fp32 weights output (exp * inv)
//         in the compute shadow (1 KB slab per chunk per CTA).
// ===========================================================================
#define TILE_B   (128 * 128)                 // 16384 B per operand tile
#define STG_B    (2 * TILE_B)                // 32768 per stage
#define NSTAGE   3
#define CTRL_B   1024
#define GEMM_SMEM (CTRL_B + NSTAGE * STG_B)  // 99328 -> 2 CTAs/SM

template <int MODE>
__global__ void __launch_bounds__(192, 2) gemm_hmma(float* __restrict__ Dbase,
                                                    float* __restrict__ Wbase)
{
    constexpr int  KT  = (MODE == 0) ? KD : SEQ;
    constexpr int  LDA = (MODE == 0) ? KD : SEQ;
    constexpr int  LDB = (MODE == 0) ? KD : SEQ;
    constexpr long long ABS = (MODE == 0) ? (long long)SEQ * KD : (long long)SEQ * SEQ;
    constexpr long long BBS = (MODE == 0) ? (long long)SEQ * KD : (long long)HID * SEQ;
    constexpr int  LDD = (MODE == 0) ? SEQ : HID;
    constexpr long long DBS = (long long)SEQ * LDD;
    constexpr int  NC  = KT / 64;

    extern __shared__ __align__(256) char smem[];
    const uint32_t sb = smem_u32(smem);
    // mbarriers: full[s] = sb + 16s, empty[s] = sb + 16s + 8

    const int tid  = threadIdx.x;            // 192
    const int warp = tid >> 5;               // 0..5
    const int lane = tid & 31;
    const int m0 = blockIdx.x * 128;
    const int n0 = blockIdx.y * 128;
    const int bz = blockIdx.z;

    const __half* A = ((MODE == 0) ? g_qf : g_wh) + (long long)bz * ABS + (long long)m0 * LDA;
    const __half* B = ((MODE == 0) ? g_kf : g_vt) + (long long)bz * BBS + (long long)n0 * LDB;

    if (tid == 0) {
#pragma unroll
        for (int s = 0; s < NSTAGE; s++) {
            MBARRIER_INIT(sb + 16 * s,     64); // full: 64 producer lanes
            MBARRIER_INIT(sb + 16 * s + 8, 4);  // empty: 4 consumer warps
        }
    }
    __syncthreads();

    if (warp >= 4) {
        // ------------------- producer: warp4 -> A, warp5 -> B -------------
        const __half* src = (warp == 4) ? A : B;
        const int     ld  = (warp == 4) ? LDA : LDB;
        const uint32_t tb0 = sb + CTRL_B + ((warp == 4) ? 0u : (uint32_t)TILE_B);
        // MODE 1: this CTA's flat 32768-float slab of the weights output
        const int pw = warp - 4;
        const long long slab = (MODE == 1)
            ? (long long)(bz * (gridDim.x * gridDim.y) + blockIdx.y * gridDim.x + blockIdx.x) * 32768
            : 0;
        int pph = 1;
#pragma unroll 1
        for (int c = 0; c < NC; c++) {
            const int st = (c % NSTAGE);
            MBARRIER_WAIT_PARITY(sb + 16 * st + 8, pph);
            const uint32_t tb = tb0 + st * STG_B;
            const int k0 = c * 64;
#pragma unroll
            for (int j = 0; j < 32; j++) {          // 1024 cp16 per tile / 32 lanes
                const int idx = lane + j * 32;
                const int row = idx >> 3;            // 0..127
                const int seg = idx & 7;             // 16B seg in 128B row
                const uint32_t off = (uint32_t)((row << 7) | (seg << 4));
                cp16(tb + SWZ(off), src + (long long)row * ld + k0 + seg * 8);
            }
            CPASYNC_MBAR_ARRIVE_NOINC(sb + 16 * st);

            if (MODE == 1) {
                // stream 1 KB of weights = exp * inv into d_out weights region
#pragma unroll
                for (int j = 0; j < 4; j++) {
                    const long long e = slab + c * 1024 + pw * 512 + j * 128 + lane * 4;
                    const uint2 h4 = *(const uint2*)(g_wh + e);
                    const float inv = g_rsum[(int)(e >> 11)];
                    const float2 lo = __half22float2(*(const __half2*)&h4.x);
                    const float2 hi = __half22float2(*(const __half2*)&h4.y);
                    *(float4*)(Wbase + e) =
                        make_float4(lo.x * inv, lo.y * inv, hi.x * inv, hi.y * inv);
                }
            }
            if (st == NSTAGE - 1) pph ^= 1;
        }
    } else {
        // ------------------- consumer: 2x2 warps, 64x64 tiles --------------
        const int wm = warp & 1;
        const int wn = warp >> 1;
        const int lr = lane & 15;
        const int lc = lane >> 4;

        float acc[4][8][4];
#pragma unroll
        for (int mt = 0; mt < 4; mt++)
#pragma unroll
            for (int nt = 0; nt < 8; nt++)
#pragma unroll
                for (int e = 0; e < 4; e++)
                    acc[mt][nt][e] = 0.0f;

        int cph = 0;
#pragma unroll 1
        for (int c = 0; c < NC; c++) {
            const int st = (c % NSTAGE);
            MBARRIER_WAIT_PARITY(sb + 16 * st, cph);
            const uint32_t ab = sb + CTRL_B + st * STG_B;
            const uint32_t bb = ab + TILE_B;
#pragma unroll
            for (int ks = 0; ks < 4; ks++) {
                const uint32_t kb = (uint32_t)(ks * 32 + lc * 16);
                uint32_t af[4][4];
                uint32_t bf[4][4];
#pragma unroll
                for (int mt = 0; mt < 4; mt++) {
                    const uint32_t off = (uint32_t)((wm * 64 + mt * 16 + lr) << 7) + kb;
                    LDSM4(af[mt], ab + SWZ(off));
                }
#pragma unroll
                for (int g = 0; g < 4; g++) {
                    const uint32_t off = (uint32_t)((wn * 64 + g * 16 + lr) << 7) + kb;
                    LDSM4(bf[g], bb + SWZ(off));
                }
#pragma unroll
                for (int mt = 0; mt < 4; mt++)
#pragma unroll
                    for (int g = 0; g < 4; g++) {
                        MMA16816(acc[mt][2 * g],     af[mt][0], af[mt][1], af[mt][2], af[mt][3],
                                 bf[g][0], bf[g][2]);
                        MMA16816(acc[mt][2 * g + 1], af[mt][0], af[mt][1], af[mt][2], af[mt][3],
                                 bf[g][1], bf[g][3]);
                    }
            }
            __syncwarp();
            if (elect_one())
                MBARRIER_ARRIVE(sb + 16 * st + 8);
            if (st == NSTAGE - 1) cph ^= 1;
        }

        // Epilogue
        const int tr = lane >> 2;
        const int tc = (lane & 3) * 2;
        const int mbase = m0 + wm * 64;
        const int nbase = n0 + wn * 64;
        if (MODE == 0) {
            // fp16 exp(acc/513 + 1) -> g_wh
            __half* Dh = g_wh + (long long)bz * SEQ * SEQ;
            const float s = 1.0f / 513.0f;
#pragma unroll
            for (int mt = 0; mt < 4; mt++)
#pragma unroll
                for (int nt = 0; nt < 8; nt++) {
                    const float e0 = __expf(acc[mt][nt][0] * s + 1.0f);
                    const float e1 = __expf(acc[mt][nt][1] * s + 1.0f);
                    const float e2 = __expf(acc[mt][nt][2] * s + 1.0f);
                    const float e3 = __expf(acc[mt][nt][3] * s + 1.0f);
                    const int row = mbase + mt * 16 + tr;
                    const int col = nbase + nt * 8 + tc;
                    *(__half2*)(Dh + (long long)row * SEQ + col)       = __floats2half2_rn(e0, e1);
                    *(__half2*)(Dh + (long long)(row + 8) * SEQ + col) = __floats2half2_rn(e2, e3);
                }
        } else {
            float* D = Dbase + (long long)bz * DBS;
#pragma unroll
            for (int mt = 0; mt < 4; mt++) {
                const int row = mbase + mt * 16 + tr;
                const float ia = g_rsum[bz * SEQ + row];
                const float ib = g_rsum[bz * SEQ + row + 8];
#pragma unroll
                for (int nt = 0; nt < 8; nt++) {
                    const int col = nbase + nt * 8 + tc;
                    *(float2*)(D + (long long)row * LDD + col) =
                        make_float2(acc[mt][nt][0] * ia, acc[mt][nt][1] * ia);
                    *(float2*)(D + (long long)(row + 8) * LDD + col) =
                        make_float2(acc[mt][nt][2] * ib, acc[mt][nt][3] * ib);
                }
            }
        }
    }
}

// ===========================================================================
// Kernel 4: rowsum-lite — one warp per row; writes ONLY 1/rowsum to g_rsum.
// (Weights output is streamed by GEMM2's producer warps.)
// ===========================================================================
__global__ void rowsum_kernel()
{
    const int wid  = threadIdx.x >> 5;         // 8 warps -> 8 rows per block
    const int lane = threadIdx.x & 31;
    const size_t row = (size_t)blockIdx.x * 8 + wid;
    const uint2* p4 = (const uint2*)(g_wh + row * SEQ);  // 512 half4 per row

    float s = 0.0f;
#pragma unroll
    for (int i = 0; i < 16; i++) {
        const uint2 h4 = p4[lane + 32 * i];
        const float2 lo = __half22float2(*(const __half2*)&h4.x);
        const float2 hi = __half22float2(*(const __half2*)&h4.y);
        s += (lo.x + lo.y) + (hi.x + hi.y);
    }
#pragma unroll
    for (int o = 16; o; o >>= 1) s += __shfl_xor_sync(0xffffffffu, s, o);
    if (lane == 0) g_rsum[row] = 1.0f / s;
}

// ===========================================================================
// Launch: out = [output (B*S*H fp32) | weights (B*S*S fp32)]
// ===========================================================================
extern "C" void kernel_launch(void* const* d_in, const int* in_sizes, int n_in,
                              void* d_out, int out_size)
{
    const float* Q = (const float*)d_in[0];
    const float* K = (const float*)d_in[1];
    const float* V = (const float*)d_in[2];
    float* out     = (float*)d_out;
    float* weights = out + (size_t)BATCH * SEQ * HID;

    cudaFuncSetAttribute(gemm_hmma<0>, cudaFuncAttributeMaxDynamicSharedMemorySize, GEMM_SMEM);
    cudaFuncSetAttribute(gemm_hmma<1>, cudaFuncAttributeMaxDynamicSharedMemorySize, GEMM_SMEM);

    // 0) twiddle table (once per launch; tiny)
    twiddle_init_kernel<<<3, 256>>>();

    // 1) phase features for Q and K (two rows per block)
    fft_phase_kernel<<<ROWS, 256>>>(Q, K);

    // 2) V -> fp16 transposed [b][h][j]
    {
        dim3 grid(HID / 32, SEQ / 64, BATCH);
        vtrans_kernel<<<grid, dim3(32, 8)>>>(V);
    }

    // 3) g_wh = fp16 exp(QF.KF^T/513 + 1)
    {
        dim3 grid(SEQ / 128, SEQ / 128, BATCH);
        gemm_hmma<0><<<grid, 192, GEMM_SMEM>>>(nullptr, nullptr);
    }

    // 4) rowsum-lite: 1/rowsum -> g_rsum (warp per row)
    rowsum_kernel<<<ROWS / 8, 256>>>();

    // 5) output = (diag(inv) . exp) @ V; producers stream fp32 weights
    {
        dim3 grid(SEQ / 128, HID / 128, BATCH);
        gemm_hmma<1><<<grid, 192, GEMM_SMEM>>>(out, weights);
    }
}